// round 2
// baseline (speedup 1.0000x reference)
#include <cuda_runtime.h>
#include <cuda_bf16.h>
#include <cstdint>
#include <cstddef>

#define BB 32
#define TT 512
#define DD 512
#define UU 512

// ---------------------------------------------------------------------------
// Device-global scratch (no cudaMalloc allowed)
// ---------------------------------------------------------------------------
__device__ float    g_mx[(size_t)BB * TT * 3 * UU];   // 402 MB: x@kernel + bias
__device__ float    g_rh[BB * UU];                    // r*h exchange buffer
__device__ unsigned g_cnt[4];
__device__ unsigned g_ep[4];

__device__ __forceinline__ float hsig(float x) {
    return fminf(fmaxf(fmaf(0.2f, x, 0.5f), 0.0f), 1.0f);
}

// ---------------------------------------------------------------------------
// Kernel 0: reset barrier state (runs before recurrence every replay)
// ---------------------------------------------------------------------------
__global__ void init_sync() {
    if (threadIdx.x < 4) {
        g_cnt[threadIdx.x] = 0u;
        g_ep[threadIdx.x]  = 0u;
    }
}

// ---------------------------------------------------------------------------
// Kernel 1: mx = x @ kernel + bias   (M=16384, N=1536, K=512)
// BM=128, BN=64, BK=16, 256 threads, 8x4 micro-tile
// ---------------------------------------------------------------------------
__global__ __launch_bounds__(256) void mx_gemm(const float* __restrict__ X,
                                               const float* __restrict__ W,
                                               const float* __restrict__ bias) {
    __shared__ float As[16][132];  // As[k][m], padded
    __shared__ float Bs[16][68];   // Bs[k][n], padded

    const int tid = threadIdx.x;
    const int m0  = blockIdx.y * 128;
    const int n0  = blockIdx.x * 64;
    const int tm  = tid & 15;
    const int tn  = tid >> 4;

    float acc[8][4];
#pragma unroll
    for (int i = 0; i < 8; i++)
#pragma unroll
        for (int j = 0; j < 4; j++) acc[i][j] = 0.0f;

    for (int kk = 0; kk < DD; kk += 16) {
#pragma unroll
        for (int jj = 0; jj < 2; jj++) {
            int idx = tid + jj * 256;          // 0..511
            int r   = idx >> 2;                // 0..127
            int kq  = (idx & 3) << 2;          // 0,4,8,12
            float4 v = *(const float4*)&X[(size_t)(m0 + r) * DD + kk + kq];
            As[kq + 0][r] = v.x;
            As[kq + 1][r] = v.y;
            As[kq + 2][r] = v.z;
            As[kq + 3][r] = v.w;
        }
        {
            int kr = tid >> 4;
            int nq = (tid & 15) << 2;
            float4 v = *(const float4*)&W[(size_t)(kk + kr) * (3 * UU) + n0 + nq];
            *(float4*)&Bs[kr][nq] = v;
        }
        __syncthreads();

#pragma unroll
        for (int k = 0; k < 16; k++) {
            float4 a0 = *(const float4*)&As[k][tm << 2];
            float4 a1 = *(const float4*)&As[k][64 + (tm << 2)];
            float4 b0 = *(const float4*)&Bs[k][tn << 2];
            float af[8] = {a0.x, a0.y, a0.z, a0.w, a1.x, a1.y, a1.z, a1.w};
            float bf[4] = {b0.x, b0.y, b0.z, b0.w};
#pragma unroll
            for (int i = 0; i < 8; i++)
#pragma unroll
                for (int j = 0; j < 4; j++) acc[i][j] = fmaf(af[i], bf[j], acc[i][j]);
        }
        __syncthreads();
    }

    float4 bv = *(const float4*)&bias[n0 + (tn << 2)];
#pragma unroll
    for (int i = 0; i < 8; i++) {
        int m = (i < 4) ? ((tm << 2) + i) : (64 + (tm << 2) + (i - 4));
        float4 o;
        o.x = acc[i][0] + bv.x;
        o.y = acc[i][1] + bv.y;
        o.z = acc[i][2] + bv.z;
        o.w = acc[i][3] + bv.w;
        *(float4*)&g_mx[(size_t)(m0 + m) * (3 * UU) + n0 + (tn << 2)] = o;
    }
}

// ---------------------------------------------------------------------------
// Kernel 2: persistent GRU recurrence
// Grid = 128 CTAs = 4 batch-groups (x8 batches) * 32 col-groups (x16 cols)
// ---------------------------------------------------------------------------
struct SM {
    float wz[512 * 16];
    float padA[16];
    float wr[512 * 16];
    float padB[16];
    float wh[512 * 16];
    float padC[16];
    float stage[512 * 12];   // [u][b], row stride 12
    float red[2048];
    float zs[8 * 16];
    float hown[8 * 16];
};
#define SMEM_BYTES ((int)sizeof(SM))

__device__ __forceinline__ void bg_sync(int bg, unsigned target) {
    __threadfence();
    __syncthreads();
    if (threadIdx.x == 0) {
        unsigned p = atomicAdd(&g_cnt[bg], 1u);
        if (p == 31u) {
            g_cnt[bg] = 0u;
            __threadfence();
            *(volatile unsigned*)&g_ep[bg] = target;
        } else {
            while (*(volatile unsigned*)&g_ep[bg] < target) { }
        }
    }
    __syncthreads();
}

__device__ __forceinline__ void stage_rows(float* stg, const float* base,
                                           size_t rowStride, int tid) {
#pragma unroll
    for (int it = 0; it < 4; it++) {
        int idx = tid + it * 256;      // 0..1023
        int b   = idx & 7;
        int ug  = idx >> 3;            // 0..127
        const float4* p = (const float4*)(base + (size_t)b * rowStride) + ug;
        float4 v = __ldcg(p);
        int u = ug << 2;
        stg[(u + 0) * 12 + b] = v.x;
        stg[(u + 1) * 12 + b] = v.y;
        stg[(u + 2) * 12 + b] = v.z;
        stg[(u + 3) * 12 + b] = v.w;
    }
}

__global__ __launch_bounds__(256) void gru_rec(const float* __restrict__ RK,
                                               float* __restrict__ out) {
    extern __shared__ char smraw[];
    SM* s = (SM*)smraw;
    const int tid = threadIdx.x;
    const int bg  = blockIdx.x >> 5;   // 0..3
    const int cg  = blockIdx.x & 31;   // 0..31
    const int gb0 = bg << 3;           // first global batch of this group
    const int j0  = cg << 4;           // first unit column of this CTA

    // Load resident weight slices (z cols j0.., r cols 512+j0.., h cols 1024+j0..)
    for (int i = tid; i < 512 * 16; i += 256) {
        int u = i >> 4, c = i & 15;
        s->wz[i] = RK[(size_t)u * 1536 + j0 + c];
        s->wr[i] = RK[(size_t)u * 1536 + 512 + j0 + c];
        s->wh[i] = RK[(size_t)u * 1536 + 1024 + j0 + c];
    }
    __syncthreads();

    unsigned tgt = 0;

    // ---- t = 0 : h_prev = 0 ----
    if (tid < 128) {
        int b  = tid >> 4, c = tid & 15;
        int gb = gb0 + b;
        size_t mrow = (size_t)gb * TT * 1536;   // t = 0
        float z  = hsig(g_mx[mrow + j0 + c]);
        float hh = tanhf(g_mx[mrow + 1024 + j0 + c]);
        out[(size_t)gb * TT * UU + j0 + c] = (1.0f - z) * hh;
    }
    bg_sync(bg, ++tgt);

#pragma unroll 1
    for (int t = 1; t < TT; t++) {
        size_t mrow_base = ((size_t)gb0 * TT + t) * 1536;

        // ---- stage h(t-1) ----
        stage_rows(s->stage, out + ((size_t)gb0 * TT + (t - 1)) * UU,
                   (size_t)TT * UU, tid);
        __syncthreads();

        // ---- phase 1: zr GEMM (8b x 32c outputs, ksplit 8, 4b x 2c micro) ----
        {
            int ks = tid >> 5;          // 0..7
            int tb = (tid >> 4) & 1;    // 0..1
            int p  = tid & 15;          // 0..15 (p<8: z pairs, p>=8: r pairs)
            const float* wp = (p < 8) ? s->wz : s->wr;
            int q = p & 7;
            float a00 = 0, a01 = 0, a10 = 0, a11 = 0;
            float a20 = 0, a21 = 0, a30 = 0, a31 = 0;
            int u0 = ks << 6;
#pragma unroll 8
            for (int uu = 0; uu < 64; uu++) {
                int u = u0 + uu;
                float4 hv = *(const float4*)&s->stage[u * 12 + (tb << 2)];
                float2 wv = *(const float2*)&wp[(u << 4) + (q << 1)];
                a00 = fmaf(hv.x, wv.x, a00); a01 = fmaf(hv.x, wv.y, a01);
                a10 = fmaf(hv.y, wv.x, a10); a11 = fmaf(hv.y, wv.y, a11);
                a20 = fmaf(hv.z, wv.x, a20); a21 = fmaf(hv.z, wv.y, a21);
                a30 = fmaf(hv.w, wv.x, a30); a31 = fmaf(hv.w, wv.y, a31);
            }
            int bb = tb << 2;
            int cc = p << 1;
            float* rd = s->red + (ks << 8);
            rd[(bb + 0) * 32 + cc + 0] = a00; rd[(bb + 0) * 32 + cc + 1] = a01;
            rd[(bb + 1) * 32 + cc + 0] = a10; rd[(bb + 1) * 32 + cc + 1] = a11;
            rd[(bb + 2) * 32 + cc + 0] = a20; rd[(bb + 2) * 32 + cc + 1] = a21;
            rd[(bb + 3) * 32 + cc + 0] = a30; rd[(bb + 3) * 32 + cc + 1] = a31;
        }
        __syncthreads();
        {
            int b  = tid >> 5;          // 0..7
            int cc = tid & 31;          // 0..31
            float sum = 0.0f;
#pragma unroll
            for (int k = 0; k < 8; k++) sum += s->red[(k << 8) + (b << 5) + cc];
            size_t mrow = mrow_base + (size_t)b * TT * 1536;
            if (cc < 16) {
                s->zs[(b << 4) + cc] = hsig(g_mx[mrow + j0 + cc] + sum);
            } else {
                int c = cc - 16;
                float r = hsig(g_mx[mrow + 512 + j0 + c] + sum);
                float h = s->stage[(j0 + c) * 12 + b];
                s->hown[(b << 4) + c] = h;
                g_rh[(size_t)(gb0 + b) * UU + j0 + c] = r * h;
            }
        }
        bg_sync(bg, ++tgt);

        // ---- stage rh ----
        stage_rows(s->stage, g_rh + (size_t)gb0 * UU, (size_t)UU, tid);
        __syncthreads();

        // ---- phase 2: h-candidate GEMM (8b x 16c, ksplit 16, 4b x 2c micro) ----
        {
            int ks = tid >> 4;          // 0..15
            int tb = (tid >> 3) & 1;
            int pc = tid & 7;
            float a00 = 0, a01 = 0, a10 = 0, a11 = 0;
            float a20 = 0, a21 = 0, a30 = 0, a31 = 0;
            int u0 = ks << 5;
#pragma unroll 8
            for (int uu = 0; uu < 32; uu++) {
                int u = u0 + uu;
                float4 hv = *(const float4*)&s->stage[u * 12 + (tb << 2)];
                float2 wv = *(const float2*)&s->wh[(u << 4) + (pc << 1)];
                a00 = fmaf(hv.x, wv.x, a00); a01 = fmaf(hv.x, wv.y, a01);
                a10 = fmaf(hv.y, wv.x, a10); a11 = fmaf(hv.y, wv.y, a11);
                a20 = fmaf(hv.z, wv.x, a20); a21 = fmaf(hv.z, wv.y, a21);
                a30 = fmaf(hv.w, wv.x, a30); a31 = fmaf(hv.w, wv.y, a31);
            }
            int bb = tb << 2;
            int cc = pc << 1;
            float* rd = s->red + (ks << 7);
            rd[(bb + 0) * 16 + cc + 0] = a00; rd[(bb + 0) * 16 + cc + 1] = a01;
            rd[(bb + 1) * 16 + cc + 0] = a10; rd[(bb + 1) * 16 + cc + 1] = a11;
            rd[(bb + 2) * 16 + cc + 0] = a20; rd[(bb + 2) * 16 + cc + 1] = a21;
            rd[(bb + 3) * 16 + cc + 0] = a30; rd[(bb + 3) * 16 + cc + 1] = a31;
        }
        __syncthreads();
        if (tid < 128) {
            int b = tid >> 4, c = tid & 15;
            float sum = 0.0f;
#pragma unroll
            for (int k = 0; k < 16; k++) sum += s->red[(k << 7) + (b << 4) + c];
            size_t mrow = mrow_base + (size_t)b * TT * 1536;
            float hh = tanhf(g_mx[mrow + 1024 + j0 + c] + sum);
            float z  = s->zs[(b << 4) + c];
            float hp = s->hown[(b << 4) + c];
            out[((size_t)(gb0 + b) * TT + t) * UU + j0 + c] =
                z * hp + (1.0f - z) * hh;
        }
        bg_sync(bg, ++tgt);
    }
}

// ---------------------------------------------------------------------------
extern "C" void kernel_launch(void* const* d_in, const int* in_sizes, int n_in,
                              void* d_out, int out_size) {
    const float* x    = (const float*)d_in[0];
    const float* ker  = (const float*)d_in[1];
    const float* rk   = (const float*)d_in[2];
    const float* bias = (const float*)d_in[3];
    float* out = (float*)d_out;
    (void)in_sizes; (void)n_in; (void)out_size;

    static bool attr_set = false;
    if (!attr_set) {
        cudaFuncSetAttribute(gru_rec, cudaFuncAttributeMaxDynamicSharedMemorySize,
                             SMEM_BYTES);
        attr_set = true;
    }

    init_sync<<<1, 32>>>();
    dim3 gg(24, 128);
    mx_gemm<<<gg, 256>>>(x, ker, bias);
    gru_rec<<<128, 256, SMEM_BYTES>>>(rk, out);
}

// round 3
// speedup vs baseline: 1.3062x; 1.3062x over previous
#include <cuda_runtime.h>
#include <cuda_bf16.h>
#include <cstdint>
#include <cstddef>

#define BB 32
#define TT 512
#define DD 512
#define UU 512

// ---------------------------------------------------------------------------
// Device-global scratch (no cudaMalloc allowed)
// ---------------------------------------------------------------------------
__device__ float    g_mx[(size_t)BB * TT * 3 * UU];   // x@kernel + bias
__device__ float    g_rh[BB * UU];                    // r*h exchange buffer
__device__ unsigned g_cnt[8];
__device__ unsigned g_ep[8];

__device__ __forceinline__ float hsig(float x) {
    return fminf(fmaxf(fmaf(0.2f, x, 0.5f), 0.0f), 1.0f);
}

// ---------------------------------------------------------------------------
// Kernel 1: mx = x @ kernel + bias   (M=16384, N=1536, K=512)
// ---------------------------------------------------------------------------
__global__ __launch_bounds__(256) void mx_gemm(const float* __restrict__ X,
                                               const float* __restrict__ W,
                                               const float* __restrict__ bias) {
    __shared__ float As[16][132];
    __shared__ float Bs[16][68];

    const int tid = threadIdx.x;
    const int m0  = blockIdx.y * 128;
    const int n0  = blockIdx.x * 64;
    const int tm  = tid & 15;
    const int tn  = tid >> 4;

    float acc[8][4];
#pragma unroll
    for (int i = 0; i < 8; i++)
#pragma unroll
        for (int j = 0; j < 4; j++) acc[i][j] = 0.0f;

    for (int kk = 0; kk < DD; kk += 16) {
#pragma unroll
        for (int jj = 0; jj < 2; jj++) {
            int idx = tid + jj * 256;
            int r   = idx >> 2;
            int kq  = (idx & 3) << 2;
            float4 v = *(const float4*)&X[(size_t)(m0 + r) * DD + kk + kq];
            As[kq + 0][r] = v.x;
            As[kq + 1][r] = v.y;
            As[kq + 2][r] = v.z;
            As[kq + 3][r] = v.w;
        }
        {
            int kr = tid >> 4;
            int nq = (tid & 15) << 2;
            float4 v = *(const float4*)&W[(size_t)(kk + kr) * (3 * UU) + n0 + nq];
            *(float4*)&Bs[kr][nq] = v;
        }
        __syncthreads();

#pragma unroll
        for (int k = 0; k < 16; k++) {
            float4 a0 = *(const float4*)&As[k][tm << 2];
            float4 a1 = *(const float4*)&As[k][64 + (tm << 2)];
            float4 b0 = *(const float4*)&Bs[k][tn << 2];
            float af[8] = {a0.x, a0.y, a0.z, a0.w, a1.x, a1.y, a1.z, a1.w};
            float bf[4] = {b0.x, b0.y, b0.z, b0.w};
#pragma unroll
            for (int i = 0; i < 8; i++)
#pragma unroll
                for (int j = 0; j < 4; j++) acc[i][j] = fmaf(af[i], bf[j], acc[i][j]);
        }
        __syncthreads();
    }

    float4 bv = *(const float4*)&bias[n0 + (tn << 2)];
#pragma unroll
    for (int i = 0; i < 8; i++) {
        int m = (i < 4) ? ((tm << 2) + i) : (64 + (tm << 2) + (i - 4));
        float4 o;
        o.x = acc[i][0] + bv.x;
        o.y = acc[i][1] + bv.y;
        o.z = acc[i][2] + bv.z;
        o.w = acc[i][3] + bv.w;
        *(float4*)&g_mx[(size_t)(m0 + m) * (3 * UU) + n0 + (tn << 2)] = o;
    }
}

// ---------------------------------------------------------------------------
// Kernel 2: persistent GRU recurrence.
// 256 CTAs = 8 batch-groups (x4 batches) * 32 col-groups (x16 cols), 2 CTAs/SM.
// ---------------------------------------------------------------------------
struct SM {
    float wz[512 * 16];
    float padA[16];          // 64 B: offsets wr by 64 mod 128 (bank interleave)
    float wr[512 * 16];
    float padB[16];
    float wh[512 * 16];
    float padC[16];
    float stage[4][516];     // h or rh, natural [b][u] layout, padded rows
    float red[8 * 128];      // cross-warp reduction scratch
    float zs[4 * 16];
    float hown[4 * 16];
};
#define SMEM_BYTES ((int)sizeof(SM))

__device__ __forceinline__ void bg_sync(int bg, unsigned target) {
    __threadfence();
    __syncthreads();
    if (threadIdx.x == 0) {
        unsigned p = atomicAdd(&g_cnt[bg], 1u);
        if (p == 31u) {
            g_cnt[bg] = 0u;
            __threadfence();
            *(volatile unsigned*)&g_ep[bg] = target;
        } else {
            while (*(volatile unsigned*)&g_ep[bg] < target) { }
        }
    }
    __syncthreads();
}

// Stage 4 rows of 512 floats (global, stride rowStride) into s->stage [b][u].
__device__ __forceinline__ void stage_load(SM* s, const float* base,
                                           size_t rowStride, int tid) {
#pragma unroll
    for (int it = 0; it < 2; it++) {
        int idx = it * 256 + tid;          // 0..511
        int b   = idx >> 7;                // 0..3
        int ug  = idx & 127;               // 0..127
        float4 v = __ldcg((const float4*)(base + (size_t)b * rowStride) + ug);
        *(float4*)&s->stage[b][ug << 2] = v;
    }
}

__global__ __launch_bounds__(256, 2) void gru_rec(const float* __restrict__ RK,
                                                  float* __restrict__ out) {
    extern __shared__ char smraw[];
    SM* s = (SM*)smraw;
    const int tid = threadIdx.x;
    const int bg  = blockIdx.x >> 5;   // 0..7
    const int cg  = blockIdx.x & 31;   // 0..31
    const int gb0 = bg << 2;           // first global batch of this group
    const int j0  = cg << 4;           // first unit column of this CTA

    // Resident weight slices
    for (int i = tid; i < 512 * 16; i += 256) {
        int u = i >> 4, c = i & 15;
        s->wz[i] = RK[(size_t)u * 1536 + j0 + c];
        s->wr[i] = RK[(size_t)u * 1536 + 512 + j0 + c];
        s->wh[i] = RK[(size_t)u * 1536 + 1024 + j0 + c];
    }

    __shared__ unsigned ep_sh;
    if (tid == 0) ep_sh = *(volatile unsigned*)&g_ep[bg];
    __syncthreads();
    unsigned tgt = ep_sh;

    const int w   = tid >> 5;
    const int l   = tid & 31;
    const int ks  = (w << 2) | (l >> 3);   // 0..31 k-split id
    const int tile = l & 7;

    // ---- t = 0 : h_prev = 0 ----
    if (tid < 64) {
        int b = tid >> 4, c = tid & 15;
        int gb = gb0 + b;
        size_t mrow = (size_t)gb * TT * 1536;
        float z  = hsig(g_mx[mrow + j0 + c]);
        float hh = tanhf(g_mx[mrow + 1024 + j0 + c]);
        out[(size_t)gb * TT * UU + j0 + c] = (1.0f - z) * hh;
    }
    bg_sync(bg, ++tgt);

#pragma unroll 1
    for (int t = 1; t < TT; t++) {
        // ---- prefetch mx gate terms for this step ----
        const int b1 = tid >> 5, cc = tid & 31;
        const int b2 = tid >> 4, c2 = tid & 15;
        float pm1 = 0.0f, pm2 = 0.0f;
        if (tid < 128) {
            size_t mrow = ((size_t)(gb0 + b1) * TT + t) * 1536;
            pm1 = __ldcg(&g_mx[mrow + (cc < 16 ? (j0 + cc)
                                               : (512 + j0 + (cc - 16)))]);
        }
        if (tid < 64) {
            size_t mrow = ((size_t)(gb0 + b2) * TT + t) * 1536;
            pm2 = __ldcg(&g_mx[mrow + 1024 + j0 + c2]);
        }

        // ---- stage h(t-1) ----
        stage_load(s, out + ((size_t)gb0 * TT + (t - 1)) * UU,
                   (size_t)TT * UU, tid);
        __syncthreads();

        // ---- phase 1: zr GEMM.  out 4b x 32c, K=512, ksplit 32 (interleaved) ----
        {
            const float* wp = (tile < 4) ? s->wz : s->wr;
            const int c0 = (tile & 3) << 2;
            float a[4][4];
#pragma unroll
            for (int b = 0; b < 4; b++)
#pragma unroll
                for (int j = 0; j < 4; j++) a[b][j] = 0.0f;
#pragma unroll
            for (int i = 0; i < 16; i++) {
                int u = ks + (i << 5);
                float4 wv = *(const float4*)&wp[(u << 4) + c0];
#pragma unroll
                for (int b = 0; b < 4; b++) {
                    float hb = s->stage[b][u];
                    a[b][0] = fmaf(hb, wv.x, a[b][0]);
                    a[b][1] = fmaf(hb, wv.y, a[b][1]);
                    a[b][2] = fmaf(hb, wv.z, a[b][2]);
                    a[b][3] = fmaf(hb, wv.w, a[b][3]);
                }
            }
            // intra-warp ksplit reduce (4 ks per warp)
#pragma unroll
            for (int b = 0; b < 4; b++)
#pragma unroll
                for (int j = 0; j < 4; j++) {
                    float v = a[b][j];
                    v += __shfl_xor_sync(0xffffffffu, v, 8);
                    v += __shfl_xor_sync(0xffffffffu, v, 16);
                    a[b][j] = v;
                }
            if (l < 8) {
                int colbase = (l < 4) ? (l << 2) : (16 + ((l - 4) << 2));
#pragma unroll
                for (int b = 0; b < 4; b++)
                    *(float4*)&s->red[(w << 7) + (b << 5) + colbase] =
                        make_float4(a[b][0], a[b][1], a[b][2], a[b][3]);
            }
        }
        __syncthreads();

        // ---- phase-1 reduction + gates ----
        if (tid < 128) {
            float sum = pm1;
#pragma unroll
            for (int k = 0; k < 8; k++) sum += s->red[(k << 7) + tid];
            if (cc < 16) {
                s->zs[(b1 << 4) + cc] = hsig(sum);
            } else {
                int c = cc - 16;
                float r  = hsig(sum);
                float hp = s->stage[b1][j0 + c];
                s->hown[(b1 << 4) + c] = hp;
                g_rh[(size_t)(gb0 + b1) * UU + j0 + c] = r * hp;
            }
        }
        bg_sync(bg, ++tgt);

        // ---- stage rh ----
        stage_load(s, g_rh + (size_t)gb0 * UU, (size_t)UU, tid);
        __syncthreads();

        // ---- phase 2: h-candidate GEMM. out 4b x 16c, ksplit 32 ----
        {
            const int c0 = tile << 1;
            float a[4][2];
#pragma unroll
            for (int b = 0; b < 4; b++) { a[b][0] = 0.0f; a[b][1] = 0.0f; }
#pragma unroll
            for (int i = 0; i < 16; i++) {
                int u = ks + (i << 5);
                float2 wv = *(const float2*)&s->wh[(u << 4) + c0];
#pragma unroll
                for (int b = 0; b < 4; b++) {
                    float hb = s->stage[b][u];
                    a[b][0] = fmaf(hb, wv.x, a[b][0]);
                    a[b][1] = fmaf(hb, wv.y, a[b][1]);
                }
            }
#pragma unroll
            for (int b = 0; b < 4; b++)
#pragma unroll
                for (int j = 0; j < 2; j++) {
                    float v = a[b][j];
                    v += __shfl_xor_sync(0xffffffffu, v, 8);
                    v += __shfl_xor_sync(0xffffffffu, v, 16);
                    a[b][j] = v;
                }
            if (l < 8) {
#pragma unroll
                for (int b = 0; b < 4; b++)
                    *(float2*)&s->red[(w << 6) + (b << 4) + c0] =
                        make_float2(a[b][0], a[b][1]);
            }
        }
        __syncthreads();

        // ---- final: hh, h update ----
        if (tid < 64) {
            float sum = pm2;
#pragma unroll
            for (int k = 0; k < 8; k++) sum += s->red[(k << 6) + tid];
            float hh = tanhf(sum);
            float z  = s->zs[tid];
            float hp = s->hown[tid];
            out[((size_t)(gb0 + b2) * TT + t) * UU + j0 + c2] =
                z * hp + (1.0f - z) * hh;
        }
        bg_sync(bg, ++tgt);
    }
}

// ---------------------------------------------------------------------------
extern "C" void kernel_launch(void* const* d_in, const int* in_sizes, int n_in,
                              void* d_out, int out_size) {
    const float* x    = (const float*)d_in[0];
    const float* ker  = (const float*)d_in[1];
    const float* rk   = (const float*)d_in[2];
    const float* bias = (const float*)d_in[3];
    float* out = (float*)d_out;
    (void)in_sizes; (void)n_in; (void)out_size;

    static bool attr_set = false;
    if (!attr_set) {
        cudaFuncSetAttribute(gru_rec, cudaFuncAttributeMaxDynamicSharedMemorySize,
                             SMEM_BYTES);
        attr_set = true;
    }

    dim3 gg(24, 128);
    mx_gemm<<<gg, 256>>>(x, ker, bias);
    gru_rec<<<256, 256, SMEM_BYTES>>>(rk, out);
}

// round 4
// speedup vs baseline: 1.3183x; 1.0093x over previous
#include <cuda_runtime.h>
#include <cuda_bf16.h>
#include <cstdint>
#include <cstddef>

#define BB 32
#define TT 512
#define DD 512
#define UU 512

// ---------------------------------------------------------------------------
// Device-global scratch (no cudaMalloc allowed)
// ---------------------------------------------------------------------------
__device__ float    g_mx[(size_t)BB * TT * 3 * UU];   // x@kernel + bias
__device__ float    g_rh[BB * UU];                    // r*h exchange buffer
__device__ unsigned g_cnt[8];
__device__ unsigned g_ep[8];

__device__ __forceinline__ float hsig(float x) {
    return fminf(fmaxf(fmaf(0.2f, x, 0.5f), 0.0f), 1.0f);
}

#define CLUSTER_SYNC() do { \
    asm volatile("barrier.cluster.arrive.aligned;" ::: "memory"); \
    asm volatile("barrier.cluster.wait.aligned;" ::: "memory"); \
} while (0)

// ---------------------------------------------------------------------------
// Kernel 1: mx = x @ kernel + bias   (M=16384, N=1536, K=512)
// ---------------------------------------------------------------------------
__global__ __launch_bounds__(256) void mx_gemm(const float* __restrict__ X,
                                               const float* __restrict__ W,
                                               const float* __restrict__ bias) {
    __shared__ float As[16][132];
    __shared__ float Bs[16][68];

    const int tid = threadIdx.x;
    const int m0  = blockIdx.y * 128;
    const int n0  = blockIdx.x * 64;
    const int tm  = tid & 15;
    const int tn  = tid >> 4;

    float acc[8][4];
#pragma unroll
    for (int i = 0; i < 8; i++)
#pragma unroll
        for (int j = 0; j < 4; j++) acc[i][j] = 0.0f;

    for (int kk = 0; kk < DD; kk += 16) {
#pragma unroll
        for (int jj = 0; jj < 2; jj++) {
            int idx = tid + jj * 256;
            int r   = idx >> 2;
            int kq  = (idx & 3) << 2;
            float4 v = *(const float4*)&X[(size_t)(m0 + r) * DD + kk + kq];
            As[kq + 0][r] = v.x;
            As[kq + 1][r] = v.y;
            As[kq + 2][r] = v.z;
            As[kq + 3][r] = v.w;
        }
        {
            int kr = tid >> 4;
            int nq = (tid & 15) << 2;
            float4 v = *(const float4*)&W[(size_t)(kk + kr) * (3 * UU) + n0 + nq];
            *(float4*)&Bs[kr][nq] = v;
        }
        __syncthreads();

#pragma unroll
        for (int k = 0; k < 16; k++) {
            float4 a0 = *(const float4*)&As[k][tm << 2];
            float4 a1 = *(const float4*)&As[k][64 + (tm << 2)];
            float4 b0 = *(const float4*)&Bs[k][tn << 2];
            float af[8] = {a0.x, a0.y, a0.z, a0.w, a1.x, a1.y, a1.z, a1.w};
            float bf[4] = {b0.x, b0.y, b0.z, b0.w};
#pragma unroll
            for (int i = 0; i < 8; i++)
#pragma unroll
                for (int j = 0; j < 4; j++) acc[i][j] = fmaf(af[i], bf[j], acc[i][j]);
        }
        __syncthreads();
    }

    float4 bv = *(const float4*)&bias[n0 + (tn << 2)];
#pragma unroll
    for (int i = 0; i < 8; i++) {
        int m = (i < 4) ? ((tm << 2) + i) : (64 + (tm << 2) + (i - 4));
        float4 o;
        o.x = acc[i][0] + bv.x;
        o.y = acc[i][1] + bv.y;
        o.z = acc[i][2] + bv.z;
        o.w = acc[i][3] + bv.w;
        *(float4*)&g_mx[(size_t)(m0 + m) * (3 * UU) + n0 + (tn << 2)] = o;
    }
}

// ===========================================================================
// PRIMARY: cluster-16 GRU recurrence. 8 clusters (= batch groups of 4), 16
// CTAs/cluster (32 unit-cols each), 512 threads, HW cluster barriers.
// ===========================================================================
struct SMC {
    float wz[512 * 32];
    float wr[512 * 32];
    float wh[512 * 32];
    float stage[4][512];
    float red[16 * 256];
    float zs[128];
    float hown[128];
};
#define SMC_BYTES ((int)sizeof(SMC))

__global__ __launch_bounds__(512, 1) void gru_clu(const float* __restrict__ RK,
                                                  float* __restrict__ out) {
    extern __shared__ char raw[];
    SMC* s = (SMC*)raw;
    const int tid = threadIdx.x;
    unsigned rank;
    asm("mov.u32 %0, %%cluster_ctarank;" : "=r"(rank));
    const int grp = blockIdx.x >> 4;       // 0..7 (cluster id)
    const int gb0 = grp << 2;              // first batch of this group
    const int j0  = (int)rank << 5;        // first unit column of this CTA

    // Resident weight slices: coalesced loads
    for (int i = tid; i < 512 * 32; i += 512) {
        int u = i >> 5, c = i & 31;
        s->wz[i] = RK[(size_t)u * 1536 + j0 + c];
        s->wr[i] = RK[(size_t)u * 1536 + 512 + j0 + c];
        s->wh[i] = RK[(size_t)u * 1536 + 1024 + j0 + c];
    }
    __syncthreads();

    const int w  = tid >> 5;
    const int l  = tid & 31;
    const int p  = l >> 3;                 // phase 0..3 -> u offset
    const int cq = (l & 7) << 2;           // column quad
    const int ubase = (w << 2) + p;        // warp covers u = 64i + 4w + p

    const int half = tid >> 7;             // (tid<256) 0:z 1:r
    const int rb   = (tid >> 5) & 3;       // batch for reduction threads
    const int rc   = tid & 31;             // column for reduction threads

    // ---- t = 0 : h_prev = 0 ----
    if (tid < 128) {
        int b = tid >> 5, c = tid & 31;
        size_t mrow = (size_t)(gb0 + b) * TT * 1536;
        float z  = hsig(g_mx[mrow + j0 + c]);
        float hh = tanhf(g_mx[mrow + 1024 + j0 + c]);
        out[(size_t)(gb0 + b) * TT * UU + j0 + c] = (1.0f - z) * hh;
    }
    CLUSTER_SYNC();

#pragma unroll 1
    for (int t = 1; t < TT; t++) {
        // ---- prefetch mx gate terms (DRAM latency hidden under zr pass) ----
        float pm1 = 0.0f, pm2 = 0.0f;
        if (tid < 256) {
            size_t mrow = ((size_t)(gb0 + rb) * TT + t) * 1536;
            pm1 = __ldcg(&g_mx[mrow + half * 512 + j0 + rc]);
            if (tid < 128) pm2 = __ldcg(&g_mx[mrow + 1024 + j0 + rc]);
        }

        // ---- stage h(t-1): 4 x 512 floats, one float4 per thread ----
        {
            int b = tid >> 7, ug = tid & 127;
            float4 v = __ldcg(
                (const float4*)(out + ((size_t)(gb0 + b) * TT + (t - 1)) * UU) + ug);
            *(float4*)&s->stage[b][ug << 2] = v;
        }
        __syncthreads();

        // ---- fused z+r pass: [4x512] @ [512x32] twice ----
        {
            float az[4][4], ar[4][4];
#pragma unroll
            for (int b = 0; b < 4; b++)
#pragma unroll
                for (int j = 0; j < 4; j++) { az[b][j] = 0.0f; ar[b][j] = 0.0f; }
#pragma unroll
            for (int i = 0; i < 8; i++) {
                int u = (i << 6) + ubase;
                float4 wzv = *(const float4*)&s->wz[(u << 5) + cq];
                float4 wrv = *(const float4*)&s->wr[(u << 5) + cq];
#pragma unroll
                for (int b = 0; b < 4; b++) {
                    float hb = s->stage[b][u];
                    az[b][0] = fmaf(hb, wzv.x, az[b][0]);
                    az[b][1] = fmaf(hb, wzv.y, az[b][1]);
                    az[b][2] = fmaf(hb, wzv.z, az[b][2]);
                    az[b][3] = fmaf(hb, wzv.w, az[b][3]);
                    ar[b][0] = fmaf(hb, wrv.x, ar[b][0]);
                    ar[b][1] = fmaf(hb, wrv.y, ar[b][1]);
                    ar[b][2] = fmaf(hb, wrv.z, ar[b][2]);
                    ar[b][3] = fmaf(hb, wrv.w, ar[b][3]);
                }
            }
            // reduce over phases p (lanes xor 8, 16)
#pragma unroll
            for (int b = 0; b < 4; b++)
#pragma unroll
                for (int j = 0; j < 4; j++) {
                    float vz = az[b][j], vr = ar[b][j];
                    vz += __shfl_xor_sync(0xffffffffu, vz, 8);
                    vz += __shfl_xor_sync(0xffffffffu, vz, 16);
                    vr += __shfl_xor_sync(0xffffffffu, vr, 8);
                    vr += __shfl_xor_sync(0xffffffffu, vr, 16);
                    az[b][j] = vz; ar[b][j] = vr;
                }
            if (l < 8) {
#pragma unroll
                for (int b = 0; b < 4; b++) {
                    *(float4*)&s->red[(w << 8) + (b << 5) + (l << 2)] =
                        make_float4(az[b][0], az[b][1], az[b][2], az[b][3]);
                    *(float4*)&s->red[(w << 8) + 128 + (b << 5) + (l << 2)] =
                        make_float4(ar[b][0], ar[b][1], ar[b][2], ar[b][3]);
                }
            }
        }
        __syncthreads();

        // ---- gate reduction: z -> zs/hown, r -> rh (global exchange) ----
        if (tid < 256) {
            float sum = pm1;
#pragma unroll
            for (int k = 0; k < 16; k++) sum += s->red[(k << 8) + tid];
            if (half == 0) {
                s->zs[(rb << 5) + rc]   = hsig(sum);
                s->hown[(rb << 5) + rc] = s->stage[rb][j0 + rc];
            } else {
                float r = hsig(sum);
                g_rh[(size_t)(gb0 + rb) * UU + j0 + rc] =
                    r * s->stage[rb][j0 + rc];
            }
        }
        CLUSTER_SYNC();

        // ---- stage rh ----
        {
            int b = tid >> 7, ug = tid & 127;
            float4 v = __ldcg((const float4*)(g_rh + (size_t)(gb0 + b) * UU) + ug);
            *(float4*)&s->stage[b][ug << 2] = v;
        }
        __syncthreads();

        // ---- h-candidate pass: [4x512] @ [512x32] ----
        {
            float ah[4][4];
#pragma unroll
            for (int b = 0; b < 4; b++)
#pragma unroll
                for (int j = 0; j < 4; j++) ah[b][j] = 0.0f;
#pragma unroll
            for (int i = 0; i < 8; i++) {
                int u = (i << 6) + ubase;
                float4 wv = *(const float4*)&s->wh[(u << 5) + cq];
#pragma unroll
                for (int b = 0; b < 4; b++) {
                    float hb = s->stage[b][u];
                    ah[b][0] = fmaf(hb, wv.x, ah[b][0]);
                    ah[b][1] = fmaf(hb, wv.y, ah[b][1]);
                    ah[b][2] = fmaf(hb, wv.z, ah[b][2]);
                    ah[b][3] = fmaf(hb, wv.w, ah[b][3]);
                }
            }
#pragma unroll
            for (int b = 0; b < 4; b++)
#pragma unroll
                for (int j = 0; j < 4; j++) {
                    float v = ah[b][j];
                    v += __shfl_xor_sync(0xffffffffu, v, 8);
                    v += __shfl_xor_sync(0xffffffffu, v, 16);
                    ah[b][j] = v;
                }
            if (l < 8) {
#pragma unroll
                for (int b = 0; b < 4; b++)
                    *(float4*)&s->red[(w << 7) + (b << 5) + (l << 2)] =
                        make_float4(ah[b][0], ah[b][1], ah[b][2], ah[b][3]);
            }
        }
        __syncthreads();

        // ---- final: hh, h update, publish h(t) ----
        if (tid < 128) {
            float sum = pm2;
#pragma unroll
            for (int k = 0; k < 16; k++) sum += s->red[(k << 7) + tid];
            float hh = tanhf(sum);
            float z  = s->zs[tid];
            float hp = s->hown[tid];
            out[((size_t)(gb0 + rb) * TT + t) * UU + j0 + rc] =
                z * hp + (1.0f - z) * hh;
        }
        CLUSTER_SYNC();
    }
}

// ===========================================================================
// FALLBACK: global-software-barrier recurrence (known passing, R3)
// ===========================================================================
struct SM {
    float wz[512 * 16];
    float padA[16];
    float wr[512 * 16];
    float padB[16];
    float wh[512 * 16];
    float padC[16];
    float stage[4][516];
    float red[8 * 128];
    float zs[4 * 16];
    float hown[4 * 16];
};
#define SMEM_BYTES ((int)sizeof(SM))

__device__ __forceinline__ void bg_sync(int bg, unsigned target) {
    __threadfence();
    __syncthreads();
    if (threadIdx.x == 0) {
        unsigned p = atomicAdd(&g_cnt[bg], 1u);
        if (p == 31u) {
            g_cnt[bg] = 0u;
            __threadfence();
            *(volatile unsigned*)&g_ep[bg] = target;
        } else {
            while (*(volatile unsigned*)&g_ep[bg] < target) { }
        }
    }
    __syncthreads();
}

__device__ __forceinline__ void stage_load(SM* s, const float* base,
                                           size_t rowStride, int tid) {
#pragma unroll
    for (int it = 0; it < 2; it++) {
        int idx = it * 256 + tid;
        int b   = idx >> 7;
        int ug  = idx & 127;
        float4 v = __ldcg((const float4*)(base + (size_t)b * rowStride) + ug);
        *(float4*)&s->stage[b][ug << 2] = v;
    }
}

__global__ __launch_bounds__(256, 2) void gru_rec(const float* __restrict__ RK,
                                                  float* __restrict__ out) {
    extern __shared__ char smraw[];
    SM* s = (SM*)smraw;
    const int tid = threadIdx.x;
    const int bg  = blockIdx.x >> 5;
    const int cg  = blockIdx.x & 31;
    const int gb0 = bg << 2;
    const int j0  = cg << 4;

    for (int i = tid; i < 512 * 16; i += 256) {
        int u = i >> 4, c = i & 15;
        s->wz[i] = RK[(size_t)u * 1536 + j0 + c];
        s->wr[i] = RK[(size_t)u * 1536 + 512 + j0 + c];
        s->wh[i] = RK[(size_t)u * 1536 + 1024 + j0 + c];
    }

    __shared__ unsigned ep_sh;
    if (tid == 0) ep_sh = *(volatile unsigned*)&g_ep[bg];
    __syncthreads();
    unsigned tgt = ep_sh;

    const int w   = tid >> 5;
    const int l   = tid & 31;
    const int ks  = (w << 2) | (l >> 3);
    const int tile = l & 7;

    if (tid < 64) {
        int b = tid >> 4, c = tid & 15;
        int gb = gb0 + b;
        size_t mrow = (size_t)gb * TT * 1536;
        float z  = hsig(g_mx[mrow + j0 + c]);
        float hh = tanhf(g_mx[mrow + 1024 + j0 + c]);
        out[(size_t)gb * TT * UU + j0 + c] = (1.0f - z) * hh;
    }
    bg_sync(bg, ++tgt);

#pragma unroll 1
    for (int t = 1; t < TT; t++) {
        const int b1 = tid >> 5, cc = tid & 31;
        const int b2 = tid >> 4, c2 = tid & 15;
        float pm1 = 0.0f, pm2 = 0.0f;
        if (tid < 128) {
            size_t mrow = ((size_t)(gb0 + b1) * TT + t) * 1536;
            pm1 = __ldcg(&g_mx[mrow + (cc < 16 ? (j0 + cc)
                                               : (512 + j0 + (cc - 16)))]);
        }
        if (tid < 64) {
            size_t mrow = ((size_t)(gb0 + b2) * TT + t) * 1536;
            pm2 = __ldcg(&g_mx[mrow + 1024 + j0 + c2]);
        }

        stage_load(s, out + ((size_t)gb0 * TT + (t - 1)) * UU,
                   (size_t)TT * UU, tid);
        __syncthreads();

        {
            const float* wp = (tile < 4) ? s->wz : s->wr;
            const int c0 = (tile & 3) << 2;
            float a[4][4];
#pragma unroll
            for (int b = 0; b < 4; b++)
#pragma unroll
                for (int j = 0; j < 4; j++) a[b][j] = 0.0f;
#pragma unroll
            for (int i = 0; i < 16; i++) {
                int u = ks + (i << 5);
                float4 wv = *(const float4*)&wp[(u << 4) + c0];
#pragma unroll
                for (int b = 0; b < 4; b++) {
                    float hb = s->stage[b][u];
                    a[b][0] = fmaf(hb, wv.x, a[b][0]);
                    a[b][1] = fmaf(hb, wv.y, a[b][1]);
                    a[b][2] = fmaf(hb, wv.z, a[b][2]);
                    a[b][3] = fmaf(hb, wv.w, a[b][3]);
                }
            }
#pragma unroll
            for (int b = 0; b < 4; b++)
#pragma unroll
                for (int j = 0; j < 4; j++) {
                    float v = a[b][j];
                    v += __shfl_xor_sync(0xffffffffu, v, 8);
                    v += __shfl_xor_sync(0xffffffffu, v, 16);
                    a[b][j] = v;
                }
            if (l < 8) {
                int colbase = (l < 4) ? (l << 2) : (16 + ((l - 4) << 2));
#pragma unroll
                for (int b = 0; b < 4; b++)
                    *(float4*)&s->red[(w << 7) + (b << 5) + colbase] =
                        make_float4(a[b][0], a[b][1], a[b][2], a[b][3]);
            }
        }
        __syncthreads();

        if (tid < 128) {
            float sum = pm1;
#pragma unroll
            for (int k = 0; k < 8; k++) sum += s->red[(k << 7) + tid];
            if (cc < 16) {
                s->zs[(b1 << 4) + cc] = hsig(sum);
            } else {
                int c = cc - 16;
                float r  = hsig(sum);
                float hp = s->stage[b1][j0 + c];
                s->hown[(b1 << 4) + c] = hp;
                g_rh[(size_t)(gb0 + b1) * UU + j0 + c] = r * hp;
            }
        }
        bg_sync(bg, ++tgt);

        stage_load(s, g_rh + (size_t)gb0 * UU, (size_t)UU, tid);
        __syncthreads();

        {
            const int c0 = tile << 1;
            float a[4][2];
#pragma unroll
            for (int b = 0; b < 4; b++) { a[b][0] = 0.0f; a[b][1] = 0.0f; }
#pragma unroll
            for (int i = 0; i < 16; i++) {
                int u = ks + (i << 5);
                float2 wv = *(const float2*)&s->wh[(u << 4) + c0];
#pragma unroll
                for (int b = 0; b < 4; b++) {
                    float hb = s->stage[b][u];
                    a[b][0] = fmaf(hb, wv.x, a[b][0]);
                    a[b][1] = fmaf(hb, wv.y, a[b][1]);
                }
            }
#pragma unroll
            for (int b = 0; b < 4; b++)
#pragma unroll
                for (int j = 0; j < 2; j++) {
                    float v = a[b][j];
                    v += __shfl_xor_sync(0xffffffffu, v, 8);
                    v += __shfl_xor_sync(0xffffffffu, v, 16);
                    a[b][j] = v;
                }
            if (l < 8) {
#pragma unroll
                for (int b = 0; b < 4; b++)
                    *(float2*)&s->red[(w << 6) + (b << 4) + c0] =
                        make_float2(a[b][0], a[b][1]);
            }
        }
        __syncthreads();

        if (tid < 64) {
            float sum = pm2;
#pragma unroll
            for (int k = 0; k < 8; k++) sum += s->red[(k << 6) + tid];
            float hh = tanhf(sum);
            float z  = s->zs[tid];
            float hp = s->hown[tid];
            out[((size_t)(gb0 + b2) * TT + t) * UU + j0 + c2] =
                z * hp + (1.0f - z) * hh;
        }
        bg_sync(bg, ++tgt);
    }
}

// ---------------------------------------------------------------------------
extern "C" void kernel_launch(void* const* d_in, const int* in_sizes, int n_in,
                              void* d_out, int out_size) {
    const float* x    = (const float*)d_in[0];
    const float* ker  = (const float*)d_in[1];
    const float* rk   = (const float*)d_in[2];
    const float* bias = (const float*)d_in[3];
    float* out = (float*)d_out;
    (void)in_sizes; (void)n_in; (void)out_size;

    static int mode = -1;
    if (mode < 0) {
        mode = 0;
        cudaError_t e1 = cudaFuncSetAttribute(
            gru_clu, cudaFuncAttributeMaxDynamicSharedMemorySize, SMC_BYTES);
        cudaError_t e2 = cudaFuncSetAttribute(
            gru_clu, cudaFuncAttributeNonPortableClusterSizeAllowed, 1);
        if (e1 == cudaSuccess && e2 == cudaSuccess) {
            cudaLaunchConfig_t cfg = {};
            cfg.gridDim  = dim3(128, 1, 1);
            cfg.blockDim = dim3(512, 1, 1);
            cfg.dynamicSmemBytes = SMC_BYTES;
            cudaLaunchAttribute attr[1];
            attr[0].id = cudaLaunchAttributeClusterDimension;
            attr[0].val.clusterDim.x = 16;
            attr[0].val.clusterDim.y = 1;
            attr[0].val.clusterDim.z = 1;
            cfg.attrs = attr;
            cfg.numAttrs = 1;
            int nclu = 0;
            cudaError_t e3 = cudaOccupancyMaxActiveClusters(&nclu, gru_clu, &cfg);
            if (e3 == cudaSuccess && nclu >= 8) mode = 1;
        }
        cudaGetLastError();  // clear any sticky error from probing
        cudaFuncSetAttribute(gru_rec, cudaFuncAttributeMaxDynamicSharedMemorySize,
                             SMEM_BYTES);
    }

    dim3 gg(24, 128);
    mx_gemm<<<gg, 256>>>(x, ker, bias);

    if (mode == 1) {
        cudaLaunchConfig_t cfg = {};
        cfg.gridDim  = dim3(128, 1, 1);
        cfg.blockDim = dim3(512, 1, 1);
        cfg.dynamicSmemBytes = SMC_BYTES;
        cudaLaunchAttribute attr[1];
        attr[0].id = cudaLaunchAttributeClusterDimension;
        attr[0].val.clusterDim.x = 16;
        attr[0].val.clusterDim.y = 1;
        attr[0].val.clusterDim.z = 1;
        cfg.attrs = attr;
        cfg.numAttrs = 1;
        cudaLaunchKernelEx(&cfg, gru_clu, rk, out);
    } else {
        gru_rec<<<256, 256, SMEM_BYTES>>>(rk, out);
    }
}